// round 8
// baseline (speedup 1.0000x reference)
#include <cuda_runtime.h>
#include <cstdint>

#define NEG   (-1e30f)
#define LOG2E (1.4426950408889634f)
#define LN2   (0.6931471805599453f)

// Fixed problem shape (B=32, T=1024, V=1000, L=128); scratch sized to max.
#define MAXB 32
#define MAXT 1024
#define MAXL 128
#define ESTR 132     // padded emission row stride (floats): 129 used
#define CH   8       // timesteps staged per SMEM chunk
#define CHF  (CH * ESTR)        // floats per chunk (1056)
#define CHV  (CHF / 4)          // float4 per chunk (264)

// Static scratch (no allocation allowed anywhere).
__device__ float g_emit[(size_t)MAXB * MAXT * ESTR];
__device__ float g_res[MAXB];

__device__ __forceinline__ float lse2_2(float a, float b) {
    float m = fmaxf(a, b);
    float s = exp2f(a - m) + exp2f(b - m);
    return m + __log2f(s);
}
__device__ __forceinline__ float lse3_2(float a, float b, float c) {
    float m = fmaxf(a, fmaxf(b, c));
    float s = exp2f(a - m) + exp2f(b - m) + exp2f(c - m);
    return m + __log2f(s);
}

// ---------------------------------------------------------------------------
// Kernel A: one WARP per (b,t) row. Single pass over V=1000 in registers,
// warp-shuffle reductions only. Emits log2-domain log-softmax for the 129
// needed tokens (blank + L labels) into g_emit.
// ---------------------------------------------------------------------------
__global__ void __launch_bounds__(128) lse_gather_kernel(
    const float* __restrict__ pred,
    const int*   __restrict__ target,
    int T, int V, int L, int nrows)
{
    const int warp = blockIdx.x * (blockDim.x >> 5) + (threadIdx.x >> 5);
    if (warp >= nrows) return;
    const int lane = threadIdx.x & 31;
    const int b = warp / T;

    const float* __restrict__ row = pred + (size_t)warp * V;
    const float4* __restrict__ row4 = (const float4*)row;
    const int nvec = V >> 2;     // 250

    float4 v[8];
    #pragma unroll
    for (int i = 0; i < 8; ++i) {
        const int idx = lane + (i << 5);
        v[i] = (idx < nvec) ? row4[idx] : make_float4(NEG, NEG, NEG, NEG);
    }

    float m = NEG;
    #pragma unroll
    for (int i = 0; i < 8; ++i)
        m = fmaxf(m, fmaxf(fmaxf(v[i].x, v[i].y), fmaxf(v[i].z, v[i].w)));
    #pragma unroll
    for (int o = 16; o > 0; o >>= 1) m = fmaxf(m, __shfl_xor_sync(0xffffffffu, m, o));

    const float m2 = m * LOG2E;
    float sum = 0.f;
    #pragma unroll
    for (int i = 0; i < 8; ++i) {
        sum += exp2f(fmaf(v[i].x, LOG2E, -m2)) + exp2f(fmaf(v[i].y, LOG2E, -m2))
             + exp2f(fmaf(v[i].z, LOG2E, -m2)) + exp2f(fmaf(v[i].w, LOG2E, -m2));
    }
    #pragma unroll
    for (int o = 16; o > 0; o >>= 1) sum += __shfl_xor_sync(0xffffffffu, sum, o);

    const float lse2 = m2 + __log2f(sum);   // log2(sum_v exp(x_v))

    float* __restrict__ erow = g_emit + (size_t)warp * ESTR;
    const int* __restrict__ tgt = target + (size_t)b * L;
    for (int j = lane; j <= L; j += 32) {
        const int tok = (j == 0) ? 0 : tgt[j - 1];
        erow[j] = fmaf(row[tok], LOG2E, -lse2);
    }
}

// ---------------------------------------------------------------------------
// Kernel B: W-CTC forward DP. One block per batch; one thread per
// (label s=2i, blank s=2i+1) PAIR -> 129 active threads, 5 warps total.
// Alpha kept in two stride-1 shared arrays (even/odd states) with a 1-slot
// NEG sentinel; emissions staged through a double-buffered SMEM chunk of 8
// timesteps (LDG issued a full chunk ahead). Label update = lse3, blank
// update = lse2 (blanks have no skip edge). ONE __syncthreads per step.
// endstar accumulated by a tail lane of warp 4 (off the main lanes).
// ---------------------------------------------------------------------------
#define HELPER_TID 132

__global__ void __launch_bounds__(160) wctc_dp_kernel(
    const int* __restrict__ target,
    const int* __restrict__ tlen,
    int T, int L)
{
    const int b   = blockIdx.x;
    const int tid = threadIdx.x;

    __shared__ float aE[2][MAXL + 2];   // even states s=2i at idx i+1; [0]=NEG sentinel
    __shared__ float aO[2][MAXL + 2];   // odd  states s=2i+1 at idx i+1
    __shared__ float e_sh[2][CHF];      // staged emission chunks
    __shared__ int   tg[MAXL];

    for (int k = tid; k < L; k += blockDim.x) tg[k] = target[(size_t)b * L + k];
    if (tid == 0) {
        aE[0][0] = NEG; aE[1][0] = NEG;
        aO[0][0] = NEG; aO[1][0] = NEG;
    }
    __syncthreads();

    const int  tl       = tlen[b];
    const int  i        = tid;            // pair index
    const bool isMain   = (i <= L);       // pairs 0..128
    const bool valid    = (i <= tl);      // both states of pair valid iff i<=tl
    const bool isHelper = (tid == HELPER_TID);
    bool skip = false;
    if (isMain && i >= 1) skip = (i == 1) || (tg[i - 1] != tg[i - 2]);

    const float*  __restrict__ erow  = g_emit + (size_t)b * T * ESTR;
    const float4* __restrict__ erow4 = (const float4*)erow;

    // ---- t = 0 init into buffer 0 ----
    if (isMain) {
        float a0 = NEG, b0 = NEG;
        if (i == 0) { a0 = 0.f; b0 = erow[0]; }   // star, first blank
        if (i == 1) a0 = erow[1];                 // first label
        if (!valid) { a0 = NEG; b0 = NEG; }
        aE[0][i + 1] = a0;
        aO[0][i + 1] = b0;
    }
    float es = NEG;                               // endstar acc (helper only)

    // Preload chunk 0 (264 float4 with 160 threads: idx tid and tid+160)
    float4 ld0 = make_float4(0.f, 0.f, 0.f, 0.f);
    float4 ld1 = make_float4(0.f, 0.f, 0.f, 0.f);
    ld0 = erow4[tid];
    if (tid + 160 < CHV) ld1 = erow4[tid + 160];

    const int nchunks = T / CH;          // 128
    int cur = 0;

    for (int c = 0; c < nchunks; ++c) {
        const int pb = c & 1;
        ((float4*)e_sh[pb])[tid] = ld0;
        if (tid + 160 < CHV) ((float4*)e_sh[pb])[tid + 160] = ld1;
        if (c + 1 < nchunks) {
            const size_t base = (size_t)(c + 1) * CHV;
            ld0 = erow4[base + tid];
            if (tid + 160 < CHV) ld1 = erow4[base + tid + 160];
        }
        __syncthreads();

        #pragma unroll
        for (int tc = 0; tc < CH; ++tc) {
            const int t = c * CH + tc;
            if (t == 0) continue;        // uniform across block (chunk 0 only)

            const float* __restrict__ E = e_sh[pb] + tc * ESTR;
            float* CE = aE[cur];       float* CO = aO[cur];
            float* NE = aE[cur ^ 1];   float* NO = aO[cur ^ 1];

            if (isMain) {
                const float aOld = CE[i + 1];
                const float bOld = CO[i + 1];
                const float aLft = CE[i];
                const float bLft = CO[i];
                const float eL   = E[i];
                const float eB   = E[0];
                float lab = eL + lse3_2(aOld, bLft, skip ? aLft : NEG);
                if (i == 0) lab = aOld;                 // star: self-loop, emission 0
                float blk = eB + lse2_2(bOld, aOld);
                if (!valid) { lab = NEG; blk = NEG; }
                NE[i + 1] = lab;
                NO[i + 1] = blk;
            }
            if (isHelper)                                // absorb alpha_{t-1}[ll], [lb]
                es = lse3_2(es, CE[tl + 1], CO[tl + 1]);
            __syncthreads();
            cur ^= 1;
        }
    }

    if (isHelper) {
        const float tot2 = lse3_2(aE[cur][tl + 1], aO[cur][tl + 1], es);  // log2 total
        g_res[b] = (-tot2 * LN2) / (float)tl;            // nll / target_length
    }
}

// ---------------------------------------------------------------------------
// Kernel C: mean over batch -> scalar output.
// ---------------------------------------------------------------------------
__global__ void __launch_bounds__(32) finalize_kernel(float* __restrict__ out, int B)
{
    float v = 0.f;
    for (int i = threadIdx.x; i < B; i += 32) v += g_res[i];
    #pragma unroll
    for (int o = 16; o > 0; o >>= 1) v += __shfl_xor_sync(0xffffffffu, v, o);
    if (threadIdx.x == 0) out[0] = v / (float)B;
}

extern "C" void kernel_launch(void* const* d_in, const int* in_sizes, int n_in,
                              void* d_out, int out_size)
{
    const float* pred   = (const float*)d_in[0];   // (B,T,V) fp32
    const int*   target = (const int*)d_in[1];     // (B,L)  int32
    const int*   tlen   = (const int*)d_in[2];     // (B,)   int32

    const int B = in_sizes[2];
    const int L = in_sizes[1] / B;
    const int V = 1000;
    const int T = in_sizes[0] / (B * V);
    const int nrows = B * T;

    lse_gather_kernel<<<(nrows + 3) / 4, 128>>>(pred, target, T, V, L, nrows);
    wctc_dp_kernel<<<B, 160>>>(target, tlen, T, L);
    finalize_kernel<<<1, 32>>>((float*)d_out, B);
}